// round 15
// baseline (speedup 1.0000x reference)
#include <cuda_runtime.h>
#include <cstdint>

#define DIM 85
#define B_ROWS 262144
#define TROWS 32
#define THREADS 160                // 4 consumer warps + 1 producer warp
#define NWC 4
#define NT (B_ROWS / TROWS)        // 8192 tiles
#define GRID 740                   // 5 persistent CTAs per SM
#define TILE_F (TROWS * DIM)       // 2720 floats
#define TILE_B (TILE_F * 4)        // 10880 bytes
#define STAGE_B (2 * TILE_B)       // 21760 bytes (in + tg)

#define OFF_FULL  0                // full[2] @ 0,8
#define OFF_EMPTY 16               // empty[2] @ 16,24
#define OFF_DATA  32
#define SMEM_TOTAL (OFF_DATA + 2 * STAGE_B)   // 43552 B -> 5 CTAs/SM

__device__ float g_partials[GRID];
__device__ int   g_count = 0;

__device__ __forceinline__ void mbar_init(uint32_t mbar, uint32_t cnt) {
    asm volatile("mbarrier.init.shared.b64 [%0], %1;" :: "r"(mbar), "r"(cnt) : "memory");
}
__device__ __forceinline__ void mbar_expect_tx(uint32_t mbar, uint32_t bytes) {
    asm volatile("mbarrier.arrive.expect_tx.shared.b64 _, [%0], %1;"
                 :: "r"(mbar), "r"(bytes) : "memory");
}
__device__ __forceinline__ void mbar_arrive(uint32_t mbar) {
    asm volatile("mbarrier.arrive.release.cta.shared::cta.b64 _, [%0];"
                 :: "r"(mbar) : "memory");
}
__device__ __forceinline__ void mbar_wait(uint32_t mbar, uint32_t parity) {
    asm volatile(
        "{\n\t"
        ".reg .pred P;\n\t"
        "W_%=:\n\t"
        "mbarrier.try_wait.parity.acquire.cta.shared::cta.b64 P, [%0], %1, 0x989680;\n\t"
        "@P bra D_%=;\n\t"
        "bra W_%=;\n\t"
        "D_%=:\n\t"
        "}" :: "r"(mbar), "r"(parity) : "memory");
}
__device__ __forceinline__ void bulk_g2s(uint32_t dst, const void* src,
                                         uint32_t bytes, uint32_t mbar) {
    asm volatile(
        "cp.async.bulk.shared::cta.global.mbarrier::complete_tx::bytes [%0], [%1], %2, [%3];"
        :: "r"(dst), "l"(src), "r"(bytes), "r"(mbar) : "memory");
}

__global__ __launch_bounds__(THREADS)
void qfd_dw(const float* __restrict__ in, const float* __restrict__ tg,
            float* __restrict__ out)
{
    extern __shared__ __align__(16) unsigned char smraw[];
    __shared__ float warp_part[THREADS / 32];
    __shared__ bool  s_is_last;

    const int tid  = threadIdx.x;
    const int wid  = tid >> 5;
    const int lane = tid & 31;

    const uint32_t full0  = (uint32_t)__cvta_generic_to_shared(smraw + OFF_FULL);
    const uint32_t empty0 = (uint32_t)__cvta_generic_to_shared(smraw + OFF_EMPTY);
    const uint32_t data_s = (uint32_t)__cvta_generic_to_shared(smraw + OFF_DATA);

    if (tid == 0) {
#pragma unroll
        for (int s = 0; s < 2; s++) {
            mbar_init(full0  + 8u * s, 1);
            mbar_init(empty0 + 8u * s, NWC);
        }
        asm volatile("fence.proxy.async.shared::cta;" ::: "memory");
    }
    __syncthreads();

    const int t0 = blockIdx.x;
    float acc = 0.0f;

    if (wid == NWC) {
        // ================= producer warp (single lane) =================
        if (lane == 0) {
            int it = 0;
            for (int t = t0; t < NT; t += GRID, it++) {
                const int s = it & 1;
                const int r = it >> 1;                 // refill round for stage s
                if (r > 0)
                    mbar_wait(empty0 + 8u * s, (uint32_t)((r - 1) & 1));
                uint32_t mb = full0 + 8u * s;
                uint32_t ds = data_s + (uint32_t)(s * STAGE_B);
                mbar_expect_tx(mb, STAGE_B);
                bulk_g2s(ds,          in + (size_t)t * TILE_F, TILE_B, mb);
                bulk_g2s(ds + TILE_B, tg + (size_t)t * TILE_F, TILE_B, mb);
            }
        }
    } else {
        // ================= consumer warps (warp-private 8 rows) =================
        const int r8 = lane >> 2;                      // row within warp: 0..7
        const int s4 = lane & 3;                       // segment: 0..3
        // kbeg = {0,24,48,72}; bank = 21*(8w+r8) + kbeg + k — conflict-free:
        // kbeg mod 32 in {0,8,16,24} (multiples of 8, distinct), 21r mod 8 bijective.
        const int kbeg = 24 * s4;
        const int kcnt = (s4 == 3) ? 13 : 24;
        const float fkbeg = (float)kbeg;
        const int row  = wid * 8 + r8;
        const int roff = row * DIM + kbeg;

        int it = 0;
        for (int t = t0; t < NT; t += GRID, it++) {
            const int s  = it & 1;
            const int ph = (it >> 1) & 1;
            mbar_wait(full0 + 8u * s, (uint32_t)ph);

            const float* in_sm = (const float*)(smraw + OFF_DATA + s * STAGE_B);
            const float* tg_sm = (const float*)(smraw + OFF_DATA + s * STAGE_B + TILE_B);
            const float* ri = in_sm + roff;
            const float* rt = tg_sm + roff;

            float P = 0.0f, Tn = 0.0f, U = 0.0f;       // Tn = -T (absolute moment)
#pragma unroll
            for (int k = 0; k < 24; k++) {
                if (k < kcnt) {
                    float d  = fabsf(ri[k] - rt[k]);
                    float fk = fkbeg + (float)k;
                    U  = fmaf(d, fmaf(fk, P, Tn), U);
                    P += d;
                    Tn = fmaf(-fk, d, Tn);
                }
            }
            // this warp is done reading stage s — signal immediately
            if (lane == 0)
                mbar_arrive(empty0 + 8u * s);

            float T = -Tn;
            // ordered merge of 4 segments across lanes (masks 1,2), register-only
#pragma unroll
            for (int m = 1; m < 4; m <<= 1) {
                float Po = __shfl_xor_sync(0xffffffffu, P, m);
                float To = __shfl_xor_sync(0xffffffffu, T, m);
                float Uo = __shfl_xor_sync(0xffffffffu, U, m);
                float c  = fmaf(P, To, -(T * Po));     // P_low*T_high - T_low*P_high
                U += Uo + ((s4 & m) ? -c : c);
                P += Po;
                T += To;
            }
            if (s4 == 0)
                acc += fmaf(P, P, -(2.0f / (float)DIM) * U);
        }
    }

    // ---- deterministic block reduce over all 5 warps ----
    __syncthreads();
    for (int o = 16; o; o >>= 1)
        acc += __shfl_down_sync(0xffffffffu, acc, o);
    if (lane == 0)
        warp_part[wid] = acc;
    __syncthreads();

    if (tid == 0) {
        float sum = 0.0f;
#pragma unroll
        for (int i = 0; i < THREADS / 32; i++)
            sum += warp_part[i];
        g_partials[blockIdx.x] = sum;
        __threadfence();
        int old = atomicAdd(&g_count, 1);
        s_is_last = (old == GRID - 1);
    }
    __syncthreads();

    // ---- last-arriving block: final deterministic reduce in double ----
    if (s_is_last) {
        __shared__ double sd[THREADS];
        double a = 0.0;
#pragma unroll
        for (int j = 0; j < (GRID + THREADS - 1) / THREADS; j++) {
            int i = tid + j * THREADS;
            if (i < GRID) a += (double)g_partials[i];
        }
        sd[tid] = a;
        __syncthreads();
        for (int o = 128; o; o >>= 1) {                // 160 threads: guarded fold
            if (tid < o && tid + o < THREADS) sd[tid] += sd[tid + o];
            __syncthreads();
        }
        if (tid == 0) {
            out[0] = (float)(0.1 * sd[0]);
            g_count = 0;                               // self-reset for next replay
        }
    }
}

extern "C" void kernel_launch(void* const* d_in, const int* in_sizes, int n_in,
                              void* d_out, int out_size)
{
    const float* in = (const float*)d_in[0];
    const float* tg = (const float*)d_in[1];
    float* out = (float*)d_out;

    cudaFuncSetAttribute(qfd_dw,
                         cudaFuncAttributeMaxDynamicSharedMemorySize, SMEM_TOTAL);
    qfd_dw<<<GRID, THREADS, SMEM_TOTAL>>>(in, tg, out);
}